// round 10
// baseline (speedup 1.0000x reference)
#include <cuda_runtime.h>

#define Nn 8
#define Cc 64
#define Hh 256
#define Ww 256
#define Pp 16          // cluster: 8 col-groups x 2 ch-groups
#define WC 32
#define NT 256         // 8 warps: conv warp = 4 out-ch x 32 cols
#define HW (Hh*Ww)

// float-index smem offsets
#define WS_F 0                          // weights 6144
#define FB_F 6144                       // fn window [64 ch][34 col] (local only!)
#define Y_F(p)  (8320 + (p)*2176)       // y window, parity double-buffered
#define ML_F(p) (12672 + (p)*1024)      // mail [16 rank][64], parity buffered
#define MR_F 14720                      // mean[64] | rstd[64]
#define XW_F(p) (14848 + (p)*2176)      // residual x/f window, parity buffered
#define SMEM_BYTES (19200*4)

__device__ float g_stack[(size_t)Nn * Cc * Hh * Ww];

extern __shared__ float sm[];

__device__ __forceinline__ void carr() {
    asm volatile("barrier.cluster.arrive.aligned;" ::: "memory");
}
__device__ __forceinline__ void cwait() {
    asm volatile("barrier.cluster.wait.aligned;" ::: "memory");
}
__device__ __forceinline__ void csync() { carr(); cwait(); }
__device__ __forceinline__ unsigned mapa_rank(unsigned laddr, unsigned rank) {
    unsigned ra;
    asm("mapa.shared::cluster.u32 %0, %1, %2;" : "=r"(ra) : "r"(laddr), "r"(rank));
    return ra;
}
__device__ __forceinline__ void st_cl_f32(unsigned a, float v) {
    asm volatile("st.shared::cluster.f32 [%0], %1;" :: "r"(a), "f"(v) : "memory");
}
__device__ __forceinline__ void st_cl_b64(unsigned a, unsigned long long v) {
    asm volatile("st.shared::cluster.b64 [%0], %1;" :: "r"(a), "l"(v) : "memory");
}

// ---- packed f32x2 helpers ----
__device__ __forceinline__ unsigned long long splat2(float a) {
    unsigned long long r; unsigned u = __float_as_uint(a);
    asm("mov.b64 %0, {%1, %1};" : "=l"(r) : "r"(u));
    return r;
}
__device__ __forceinline__ void fma2(unsigned long long& d, unsigned long long a, unsigned long long b) {
    asm("fma.rn.f32x2 %0, %1, %2, %0;" : "+l"(d) : "l"(a), "l"(b));
}
__device__ __forceinline__ unsigned long long add2(unsigned long long a, unsigned long long b) {
    unsigned long long d;
    asm("add.rn.f32x2 %0, %1, %2;" : "=l"(d) : "l"(a), "l"(b));
    return d;
}
__device__ __forceinline__ unsigned long long mul2(unsigned long long a, unsigned long long b) {
    unsigned long long d;
    asm("mul.rn.f32x2 %0, %1, %2;" : "=l"(d) : "l"(a), "l"(b));
    return d;
}
__device__ __forceinline__ void unpack2(unsigned long long v, float& lo, float& hi) {
    unsigned ul, uh;
    asm("mov.b64 {%0, %1}, %2;" : "=r"(ul), "=r"(uh) : "l"(v));
    lo = __uint_as_float(ul); hi = __uint_as_float(uh);
}

// stage one row's full 64ch x 34col window (edge-masked) into smem
__device__ __forceinline__ void load_window(const float* __restrict__ src,
    int row, int w0, int tid, float* __restrict__ dsm)
{
#pragma unroll
    for (int it = 0; it < 9; it++) {
        int idx = tid + it * NT;
        if (idx < 2176) {
            int ch = idx / 34;
            int c  = idx - ch * 34;
            int gcol = w0 - 1 + c;
            float v = (gcol >= 0 && gcol < Ww)
                    ? src[(size_t)ch * HW + (size_t)row * Ww + gcol] : 0.f;
            dsm[idx] = v;
        }
    }
}

__global__ void __launch_bounds__(NT, 1) __cluster_dims__(Pp, 1, 1)
dirconv_kernel(const float* __restrict__ x, const float* __restrict__ Wg,
               float* __restrict__ out)
{
    float* Ws = sm;
    float* fb = sm + FB_F;
    const unsigned smu = (unsigned)__cvta_generic_to_shared(sm);

    const int tid  = threadIdx.x;
    const int lane = tid & 31;
    const int warp = tid >> 5;
    const int ob   = warp * 4;
    unsigned rank;
    asm("mov.u32 %0, %%cluster_ctarank;" : "=r"(rank));
    const int g     = (int)(rank >> 1);
    const int cg    = (int)(rank & 1u);
    const int cbase = cg * 32;
    const int w0    = g * WC;
    const int b     = blockIdx.x / Pp;
    const int hasL  = (g > 0), hasR = (g < 7);

    const float* xb = x + (size_t)b * Cc * HW;
    float* stk      = g_stack + (size_t)b * Cc * HW;
    float* outb     = out + (size_t)b * Cc * HW;

    const unsigned pbP  = mapa_rank(smu, rank ^ 1u);
    const unsigned basr = rank & ~1u;
    const unsigned pbL0 = mapa_rank(smu, hasL ? basr - 2u : 0u);
    const unsigned pbL1 = mapa_rank(smu, hasL ? basr - 1u : 0u);
    const unsigned pbR0 = mapa_rank(smu, hasR ? basr + 2u : 0u);
    const unsigned pbR1 = mapa_rank(smu, hasR ? basr + 3u : 0u);
    unsigned pbAll[16];
#pragma unroll
    for (int p2 = 0; p2 < 16; p2++) pbAll[p2] = mapa_rank(smu, (unsigned)p2);

    // stage weights: Ws[i*96 + tap*32 + ol] = W[cbase+ol][i][1][tap] (bias cancels in IN)
    for (int idx = tid; idx < 6144; idx += NT) {
        int i   = idx / 96;
        int rem = idx - i * 96;
        int tap = rem >> 5;
        int ol  = rem & 31;
        Ws[idx] = Wg[(size_t)(cbase + ol) * 576 + i * 9 + 3 + tap];
    }

    // f[0] = x[0]: full local window; own block to stack row 0; xwin for t=1
    load_window(xb, 0, w0, tid, fb);
    for (int idx = tid; idx < 1024; idx += NT) {
        int ch = cbase + (idx >> 5);
        int c  = idx & 31;
        stk[(size_t)ch * HW + w0 + c] = xb[(size_t)ch * HW + w0 + c];
    }
    load_window(xb, 1, w0, tid, sm + XW_F(1));

    // epilogue partition: thread -> (channel, col segment {9,9,8,8})
    const int ch_e  = tid >> 2;
    const int seg   = tid & 3;
    const int cs    = (seg < 2) ? seg * 9 : 18 + (seg - 2) * 8;
    const int clen  = (seg < 2) ? 9 : 8;
    const int own_ch = ((ch_e >> 5) == cg);

    csync();   // everyone staged

    for (int t = 1; t <= 510; ++t) {
        const int p   = t & 1;
        const int fwd = (t <= 255);
        const int row = fwd ? t : 510 - t;

        // ---- conv: lane = col, warp owns 4 out channels as 2 f32x2 pairs
        unsigned long long acc0 = 0ull, acc1 = 0ull;
#pragma unroll 8
        for (int i = 0; i < Cc; i++) {
            float a0 = fb[i * 34 + lane];
            float a1 = fb[i * 34 + lane + 1];
            float a2 = fb[i * 34 + lane + 2];
            unsigned long long s0 = splat2(a0), s1 = splat2(a1), s2 = splat2(a2);
            const float* wp = Ws + i * 96 + ob;
            ulonglong2 t0 = *(const ulonglong2*)(wp);
            ulonglong2 t1 = *(const ulonglong2*)(wp + 32);
            ulonglong2 t2 = *(const ulonglong2*)(wp + 64);
            fma2(acc0, s0, t0.x); fma2(acc1, s0, t0.y);
            fma2(acc0, s1, t1.x); fma2(acc1, s1, t1.y);
            fma2(acc0, s2, t2.x); fma2(acc1, s2, t2.y);
        }

        // ---- publish y (local + partner + edge cols to neighbor pairs)
        float av[4];
        unpack2(acc0, av[0], av[1]);
        unpack2(acc1, av[2], av[3]);
        {
            float* yL = sm + Y_F(p);
            const unsigned yBB = (unsigned)(Y_F(p) * 4);
#pragma unroll
            for (int k = 0; k < 4; k++) {
                int o = (cbase + ob + k) * 34 + 1 + lane;
                yL[o] = av[k];
                st_cl_f32(pbP + yBB + (unsigned)o * 4u, av[k]);
            }
            if (lane == 0 && hasL) {
#pragma unroll
                for (int k = 0; k < 4; k++) {
                    unsigned o = yBB + (unsigned)((cbase + ob + k) * 34 + 33) * 4u;
                    st_cl_f32(pbL0 + o, av[k]); st_cl_f32(pbL1 + o, av[k]);
                }
            }
            if (lane == 31 && hasR) {
#pragma unroll
                for (int k = 0; k < 4; k++) {
                    unsigned o = yBB + (unsigned)((cbase + ob + k) * 34 + 0) * 4u;
                    st_cl_f32(pbR0 + o, av[k]); st_cl_f32(pbR1 + o, av[k]);
                }
            }
        }

        // ---- butterfly reduce + all-to-all mail (15 remote ranks)
        {
            unsigned long long s0r = acc0, s1r = acc1;
            unsigned long long q0r = mul2(acc0, acc0), q1r = mul2(acc1, acc1);
#pragma unroll
            for (int off = 16; off >= 1; off >>= 1) {
                s0r = add2(s0r, __shfl_xor_sync(0xffffffffu, s0r, off));
                s1r = add2(s1r, __shfl_xor_sync(0xffffffffu, s1r, off));
                q0r = add2(q0r, __shfl_xor_sync(0xffffffffu, q0r, off));
                q1r = add2(q1r, __shfl_xor_sync(0xffffffffu, q1r, off));
            }
            if (lane < 4) {
                int j   = lane & 1;
                int isq = lane >> 1;
                unsigned long long val = isq ? (j ? q1r : q0r) : (j ? s1r : s0r);
                unsigned moff = (unsigned)(ML_F(p) * 4) +
                    (unsigned)((int)rank * 64 + isq * 32 + ob + 2 * j) * 4u;
                *(unsigned long long*)((char*)sm + moff) = val;   // local slot
#pragma unroll
                for (int p2 = 0; p2 < 16; p2++)
                    if (p2 != (int)rank) st_cl_b64(pbAll[p2] + moff, val);
            }
        }

        // ---- the ONE rendezvous; residual prefetch hides its latency
        carr();
        if (t < 510 && t != 255) {
            int tn   = t + 1;
            int nfwd = (tn <= 255);
            load_window(nfwd ? xb : stk, nfwd ? tn : 510 - tn, w0, tid,
                        sm + XW_F(p ^ 1));
        }
        cwait();
        __syncthreads();
        if (t == 255)   // stk row 254 written by peers; visible only after this wait
            load_window(stk, 254, w0, tid, sm + XW_F(0));

        // ---- stats for ALL 64 channels (local mail)
        if (tid < 64) {
            int ch  = tid;
            int par = ch >> 5;
            const float* ml = sm + ML_F(p);
            float sv = 0.f, qv = 0.f;
#pragma unroll
            for (int gg = 0; gg < 8; gg++) {
                int r2 = 2 * gg + par;
                sv += ml[r2 * 64 + (ch & 31)];
                qv += ml[r2 * 64 + 32 + (ch & 31)];
            }
            float mean = sv * (1.f / 256.f);
            float var  = qv * (1.f / 256.f) - mean * mean;
            sm[MR_F + ch]      = mean;
            sm[MR_F + 64 + ch] = rsqrtf(var + 1e-5f);
        }
        __syncthreads();

        // ---- replicated epilogue: full 64x34 window -> fb (local), own block -> GMEM
        {
            const float* yb = sm + Y_F(p);
            const float* xw = sm + XW_F(p);
            float m  = sm[MR_F + ch_e];
            float rs = sm[MR_F + 64 + ch_e];
            float* __restrict__ dst = fwd ? stk : outb;
            const size_t rowbase = (size_t)ch_e * HW + (size_t)row * Ww;
#pragma unroll
            for (int i2 = 0; i2 < 9; i2++) {
                if (i2 < clen) {
                    int c = cs + i2;
                    float y = yb[ch_e * 34 + c];
                    float v = (y - m) * rs;
                    v = v > 0.f ? v : (__expf(v) - 1.f);
                    int pad = (g == 0 && c == 0) || (g == 7 && c == 33);
                    float fn = pad ? 0.f : (v + xw[ch_e * 34 + c]);
                    fb[ch_e * 34 + c] = fn;
                    if (own_ch && c >= 1 && c <= 32) {
                        dst[rowbase + (w0 - 1 + c)] = fn;
                        if (t == 255) outb[rowbase + (w0 - 1 + c)] = fn;
                    }
                }
            }
        }
        __syncthreads();   // fb complete before next conv
    }
}

extern "C" void kernel_launch(void* const* d_in, const int* in_sizes, int n_in,
                              void* d_out, int out_size)
{
    (void)in_sizes; (void)n_in; (void)out_size;
    const float* x  = (const float*)d_in[0];
    const float* Wg = (const float*)d_in[1];
    // d_in[2] (bias) cancels through InstanceNorm — skipped.
    float* out = (float*)d_out;

    cudaStreamCaptureStatus cs = cudaStreamCaptureStatusNone;
    cudaStreamIsCapturing(0, &cs);
    if (cs == cudaStreamCaptureStatusNone) {
        cudaFuncSetAttribute(dirconv_kernel,
                             cudaFuncAttributeNonPortableClusterSizeAllowed, 1);
        cudaFuncSetAttribute(dirconv_kernel,
                             cudaFuncAttributeMaxDynamicSharedMemorySize, SMEM_BYTES);
    }

    dirconv_kernel<<<Nn * Pp, NT, SMEM_BYTES>>>(x, Wg, out);
}

// round 11
// speedup vs baseline: 1.2501x; 1.2501x over previous
#include <cuda_runtime.h>

#define Nn 8
#define Cc 64
#define Hh 256
#define Ww 256
#define Pp 8           // cluster: 8 column groups, each CTA = ALL 64 out-ch x 32 cols
#define WC 32
#define FSTR 34
#define NT 256         // 8 warps: warp = 8 out-ch x 32 cols
#define HW (Hh*Ww)

// float-index smem offsets
#define W1_F 0                         // tap-1 weights [64 i][64 o] = 4096
#define FB_F(b) (4096 + (b)*2176)      // fn window [64 ch][34], double buffered
#define ML_F 8448                      // mail [8 rank][sum 64 | sq 64]
#define MR_F 9472                      // mean[64] | rstd[64]
#define SM_TOT 9600
#define SMEM_BYTES (SM_TOT*4)
#define ML_B (ML_F*4)

__device__ float g_stack[(size_t)Nn * Cc * Hh * Ww];
__device__ float g_wpack[Cc * 3 * Cc];   // [i][tap][o] — o pair-contiguous

extern __shared__ float sm[];

__device__ __forceinline__ void carr() {
    asm volatile("barrier.cluster.arrive.aligned;" ::: "memory");
}
__device__ __forceinline__ void cwait() {
    asm volatile("barrier.cluster.wait.aligned;" ::: "memory");
}
__device__ __forceinline__ void csync() { carr(); cwait(); }
__device__ __forceinline__ unsigned mapa_rank(unsigned laddr, unsigned rank) {
    unsigned ra;
    asm("mapa.shared::cluster.u32 %0, %1, %2;" : "=r"(ra) : "r"(laddr), "r"(rank));
    return ra;
}
__device__ __forceinline__ void st_cl_f32(unsigned a, float v) {
    asm volatile("st.shared::cluster.f32 [%0], %1;" :: "r"(a), "f"(v) : "memory");
}
__device__ __forceinline__ void st_cl_b64(unsigned a, unsigned long long v) {
    asm volatile("st.shared::cluster.b64 [%0], %1;" :: "r"(a), "l"(v) : "memory");
}

// ---- packed f32x2 helpers ----
__device__ __forceinline__ unsigned long long splat2(float a) {
    unsigned long long r; unsigned u = __float_as_uint(a);
    asm("mov.b64 %0, {%1, %1};" : "=l"(r) : "r"(u));
    return r;
}
__device__ __forceinline__ void fma2(unsigned long long& d, unsigned long long a, unsigned long long b) {
    asm("fma.rn.f32x2 %0, %1, %2, %0;" : "+l"(d) : "l"(a), "l"(b));
}
__device__ __forceinline__ unsigned long long add2(unsigned long long a, unsigned long long b) {
    unsigned long long d;
    asm("add.rn.f32x2 %0, %1, %2;" : "=l"(d) : "l"(a), "l"(b));
    return d;
}
__device__ __forceinline__ unsigned long long mul2(unsigned long long a, unsigned long long b) {
    unsigned long long d;
    asm("mul.rn.f32x2 %0, %1, %2;" : "=l"(d) : "l"(a), "l"(b));
    return d;
}
__device__ __forceinline__ void unpack2(unsigned long long v, float& lo, float& hi) {
    unsigned ul, uh;
    asm("mov.b64 {%0, %1}, %2;" : "=r"(ul), "=r"(uh) : "l"(v));
    lo = __uint_as_float(ul); hi = __uint_as_float(uh);
}
// 16B read-only global load (weights; never written by this kernel)
__device__ __forceinline__ ulonglong2 ldg2(const float* p) {
    ulonglong2 r;
    asm("ld.global.nc.v2.u64 {%0, %1}, [%2];" : "=l"(r.x), "=l"(r.y) : "l"(p));
    return r;
}

// weight prepack: g_wpack[i*192 + tap*64 + o] = W[o][i][1][tap]
__global__ void prepack_kernel(const float* __restrict__ Wg) {
    int idx = blockIdx.x * 256 + threadIdx.x;
    if (idx < Cc * 3 * Cc) {
        int i   = idx / 192;
        int rem = idx - i * 192;
        int tap = rem >> 6;
        int o   = rem & 63;
        g_wpack[idx] = Wg[(size_t)o * 576 + i * 9 + 3 + tap];
    }
}

__global__ void __launch_bounds__(NT, 1) __cluster_dims__(Pp, 1, 1)
dirconv_kernel(const float* __restrict__ x, float* __restrict__ out)
{
    float* Ws1 = sm + W1_F;
    const unsigned smu = (unsigned)__cvta_generic_to_shared(sm);

    const int tid  = threadIdx.x;
    const int lane = tid & 31;
    const int warp = tid >> 5;
    const int ob   = warp * 8;            // warp's out-channel base (8 channels)
    unsigned rank;
    asm("mov.u32 %0, %%cluster_ctarank;" : "=r"(rank));
    const int g    = (int)rank;           // column group 0..7
    const int w0   = g * WC;
    const int b    = blockIdx.x / Pp;
    const int hasL = (g > 0), hasR = (g < 7);

    const float* xb = x + (size_t)b * Cc * HW;
    float* stk      = g_stack + (size_t)b * Cc * HW;
    float* outb     = out + (size_t)b * Cc * HW;

    const unsigned pbL = mapa_rank(smu, hasL ? rank - 1u : 0u);
    const unsigned pbR = mapa_rank(smu, hasR ? rank + 1u : 0u);
    unsigned pbAll[8];
#pragma unroll
    for (int p2 = 0; p2 < 8; p2++) pbAll[p2] = mapa_rank(smu, (unsigned)p2);

    // stage tap-1 weights to smem (taps 0/2 stream from L1 via ldg)
    for (int idx = tid; idx < 4096; idx += NT) {
        int i = idx >> 6, o = idx & 63;
        Ws1[idx] = g_wpack[i * 192 + 64 + o];
    }

    // f[0] = x[0]: full local 64ch x 34col window into fb[0]; own block -> stack row 0
    for (int idx = tid; idx < 2176; idx += NT) {
        int ch = idx / 34;
        int c  = idx - ch * 34;
        int gcol = w0 - 1 + c;
        sm[FB_F(0) + ch * FSTR + c] =
            (gcol >= 0 && gcol < Ww) ? xb[(size_t)ch * HW + gcol] : 0.f;
    }
    for (int idx = tid; idx < 2048; idx += NT) {
        int ch = idx >> 5, c = idx & 31;
        stk[(size_t)ch * HW + w0 + c] = xb[(size_t)ch * HW + w0 + c];
    }
    // zero cluster-edge halo columns in BOTH parity buffers
    if (g == 0 && tid < 64) { sm[FB_F(0) + tid * FSTR] = 0.f; sm[FB_F(1) + tid * FSTR] = 0.f; }
    if (g == 7 && tid < 64) { sm[FB_F(0) + tid * FSTR + 33] = 0.f; sm[FB_F(1) + tid * FSTR + 33] = 0.f; }

    // residual prefetch for t=1
    float xr[8], xrn[8], fn[8];
#pragma unroll
    for (int k = 0; k < 8; k++)
        xr[k] = xb[(size_t)(ob + k) * HW + (size_t)1 * Ww + w0 + lane];

    csync();   // all CTAs staged (incl. halo zero + fb windows)

    for (int t = 1; t <= 510; ++t) {
        const int p   = t & 1;
        const int fwd = (t <= 255);
        const int row = fwd ? t : 510 - t;
        const float* fbR = sm + FB_F(p ^ 1);
        float* fbW       = sm + FB_F(p);
        const unsigned fbWB = (unsigned)(FB_F(p) * 4);

        // ===== rendezvous #1 (fn(t-1) incl. halos delivered); writeback hides flight
        carr();
        if (t >= 2) {
            const int pfwd = (t - 1) <= 255;
            const int prow = pfwd ? (t - 1) : (511 - t);
            float* __restrict__ pdst = pfwd ? stk : outb;
#pragma unroll
            for (int k = 0; k < 8; k++)
                pdst[(size_t)(ob + k) * HW + (size_t)prow * Ww + w0 + lane] = fn[k];
            if (t == 256) {   // out[255] = f[255]
#pragma unroll
                for (int k = 0; k < 8; k++)
                    outb[(size_t)(ob + k) * HW + (size_t)255 * Ww + w0 + lane] = fn[k];
            }
        }
        cwait();

        // ===== conv: lane = col, warp owns 8 out-ch as 4 f32x2 pairs.
        // tap1 from smem; taps 0/2 stream from L1 (prepacked, pair-contiguous).
        unsigned long long acc0 = 0ull, acc1 = 0ull, acc2 = 0ull, acc3 = 0ull;
#pragma unroll 4
        for (int i = 0; i < Cc; i++) {
            float a0 = fbR[i * FSTR + lane];
            float a1 = fbR[i * FSTR + lane + 1];
            float a2 = fbR[i * FSTR + lane + 2];
            unsigned long long s0 = splat2(a0), s1 = splat2(a1), s2 = splat2(a2);
            const float* wg = g_wpack + i * 192 + ob;
            ulonglong2 u0 = ldg2(wg);              // tap0 ch pairs 0..3
            ulonglong2 u0b = ldg2(wg + 4);         // tap0 ch pairs 4..7
            ulonglong2 u2 = ldg2(wg + 128);        // tap2
            ulonglong2 u2b = ldg2(wg + 132);
            const ulonglong2* w1p = (const ulonglong2*)(Ws1 + i * 64 + ob);
            ulonglong2 u1 = w1p[0], u1b = w1p[1];  // tap1 (smem broadcast)
            fma2(acc0, s0, u0.x);  fma2(acc1, s0, u0.y);
            fma2(acc2, s0, u0b.x); fma2(acc3, s0, u0b.y);
            fma2(acc0, s1, u1.x);  fma2(acc1, s1, u1.y);
            fma2(acc2, s1, u1b.x); fma2(acc3, s1, u1b.y);
            fma2(acc0, s2, u2.x);  fma2(acc1, s2, u2.y);
            fma2(acc2, s2, u2b.x); fma2(acc3, s2, u2b.y);
        }

        // ===== butterfly reduce over this CTA's 32 cols (packed sum / sumsq)
        unsigned long long s0r = acc0, s1r = acc1, s2r = acc2, s3r = acc3;
        unsigned long long q0r = mul2(acc0, acc0), q1r = mul2(acc1, acc1);
        unsigned long long q2r = mul2(acc2, acc2), q3r = mul2(acc3, acc3);
#pragma unroll
        for (int off = 16; off >= 1; off >>= 1) {
            s0r = add2(s0r, __shfl_xor_sync(0xffffffffu, s0r, off));
            s1r = add2(s1r, __shfl_xor_sync(0xffffffffu, s1r, off));
            s2r = add2(s2r, __shfl_xor_sync(0xffffffffu, s2r, off));
            s3r = add2(s3r, __shfl_xor_sync(0xffffffffu, s3r, off));
            q0r = add2(q0r, __shfl_xor_sync(0xffffffffu, q0r, off));
            q1r = add2(q1r, __shfl_xor_sync(0xffffffffu, q1r, off));
            q2r = add2(q2r, __shfl_xor_sync(0xffffffffu, q2r, off));
            q3r = add2(q3r, __shfl_xor_sync(0xffffffffu, q3r, off));
        }
        // mail push: lanes 0..7 carry one b64 each to all 8 ranks
        if (lane < 8) {
            int j   = lane & 3;          // which channel pair
            int isq = lane >> 2;         // 0: sum, 1: sumsq
            unsigned long long val;
            if (isq) val = (j == 0) ? q0r : (j == 1) ? q1r : (j == 2) ? q2r : q3r;
            else     val = (j == 0) ? s0r : (j == 1) ? s1r : (j == 2) ? s2r : s3r;
            unsigned moff = (unsigned)ML_B +
                (unsigned)((int)rank * 128 + isq * 64 + ob + 2 * j) * 4u;
            *(unsigned long long*)((char*)sm + moff) = val;   // local slot
#pragma unroll
            for (int p2 = 0; p2 < 8; p2++)
                if (p2 != (int)rank) st_cl_b64(pbAll[p2] + moff, val);
        }

        // ===== rendezvous #2 (mail delivered); residual prefetch hides flight
        carr();
        if (t < 510) {
            const int tn   = t + 1;
            const int nfwd = (tn <= 255);
            const int nrow = nfwd ? tn : 510 - tn;
            const float* __restrict__ nsrc = nfwd ? xb : stk;
#pragma unroll
            for (int k = 0; k < 8; k++)
                xrn[k] = nsrc[(size_t)(ob + k) * HW + (size_t)nrow * Ww + w0 + lane];
        }
        cwait();

        // ===== per-channel stats from local mail
        if (tid < 64) {
            const float* ml = sm + ML_F;
            float sv = 0.f, qv = 0.f;
#pragma unroll
            for (int r2 = 0; r2 < 8; r2++) {
                sv += ml[r2 * 128 + tid];
                qv += ml[r2 * 128 + 64 + tid];
            }
            float mean = sv * (1.f / 256.f);
            float var  = qv * (1.f / 256.f) - mean * mean;
            sm[MR_F + tid]      = mean;
            sm[MR_F + 64 + tid] = rsqrtf(var + 1e-5f);
        }
        __syncthreads();

        // ===== epilogue: normalize + ELU + residual; local fb + halo pushes
        float av[8];
        unpack2(acc0, av[0], av[1]);
        unpack2(acc1, av[2], av[3]);
        unpack2(acc2, av[4], av[5]);
        unpack2(acc3, av[6], av[7]);
#pragma unroll
        for (int k = 0; k < 8; k++) {
            int ch = ob + k;
            float m  = sm[MR_F + ch];
            float rs = sm[MR_F + 64 + ch];
            float v = (av[k] - m) * rs;
            v = v > 0.f ? v : (__expf(v) - 1.f);
            float f = v + xr[k];
            fn[k] = f;
            fbW[ch * FSTR + 1 + lane] = f;
            if (lane == 0 && hasL)
                st_cl_f32(pbL + fbWB + (unsigned)(ch * FSTR + 33) * 4u, f);
            if (lane == 31 && hasR)
                st_cl_f32(pbR + fbWB + (unsigned)(ch * FSTR + 0) * 4u, f);
        }
#pragma unroll
        for (int k = 0; k < 8; k++) xr[k] = xrn[k];
    }

    // final writeback: fn holds row 0 (t=510 epilogue output)
#pragma unroll
    for (int k = 0; k < 8; k++)
        outb[(size_t)(ob + k) * HW + w0 + lane] = fn[k];

    // no CTA exits while peers may still push into its smem
    csync();
}

extern "C" void kernel_launch(void* const* d_in, const int* in_sizes, int n_in,
                              void* d_out, int out_size)
{
    (void)in_sizes; (void)n_in; (void)out_size;
    const float* x  = (const float*)d_in[0];
    const float* Wg = (const float*)d_in[1];
    // d_in[2] (bias) cancels through InstanceNorm — skipped.
    float* out = (float*)d_out;

    cudaStreamCaptureStatus cs = cudaStreamCaptureStatusNone;
    cudaStreamIsCapturing(0, &cs);
    if (cs == cudaStreamCaptureStatusNone)
        cudaFuncSetAttribute(dirconv_kernel,
                             cudaFuncAttributeMaxDynamicSharedMemorySize, SMEM_BYTES);

    prepack_kernel<<<(Cc * 3 * Cc + 255) / 256, 256>>>(Wg);
    dirconv_kernel<<<Nn * Pp, NT, SMEM_BYTES>>>(x, out);
}